// round 1
// baseline (speedup 1.0000x reference)
#include <cuda_runtime.h>
#include <math.h>
#include <stdint.h>

// Problem constants
#define BB 4
#define SS 2048
#define EE 1024
#define HH 8
#define DD 128
#define TT (BB*SS)          // 8192 tokens
#define EPSF 1e-5f

// ---------------- scratch (device globals; no allocations allowed) ----------
__device__ float g_Z  [TT*EE];   // tanh(x@W_ez)          [t][h*128+d]
__device__ float g_ST [TT*EE];   // scan states           [t][h*128+d]
__device__ float g_HLN[TT*EE];   // LN(states*os_diag)    [t][h*128+d]
__device__ float g_H1 [TT*EE];   // gelu FFN hidden       [t][h*128+e]
__device__ float g_G  [TT*EE];   // score-scaled h1       [t][h*128+e]
__device__ float g_P  [TT*EE];   // pre-LN output         [t][e]
__device__ float g_LG [TT*HH];   // logits
__device__ float g_SC [TT*HH];   // softmax scores
__device__ float g_V  [HH*DD];   // W2[h] @ w_att
__device__ float g_C  [HH];      // b2[h] . w_att

// ---------------- K0: precompute v[h,d] = sum_e W2[h,d,e]*w_att[e] ----------
__global__ void prep_v(const float* __restrict__ W2,
                       const float* __restrict__ b2,
                       const float* __restrict__ watt)
{
    int hh = blockIdx.x;          // 8
    int d  = threadIdx.x;         // 128
    const float* row = W2 + ((size_t)hh*DD + d)*EE;
    float a0=0.f,a1=0.f,a2=0.f,a3=0.f;
    for (int e = 0; e < EE; e += 4) {
        a0 = fmaf(row[e+0], watt[e+0], a0);
        a1 = fmaf(row[e+1], watt[e+1], a1);
        a2 = fmaf(row[e+2], watt[e+2], a2);
        a3 = fmaf(row[e+3], watt[e+3], a3);
    }
    g_V[hh*DD + d] = (a0+a1)+(a2+a3);
    if (d == 0) {
        const float* br = b2 + (size_t)hh*EE;
        float c0=0.f,c1=0.f,c2=0.f,c3=0.f;
        for (int e = 0; e < EE; e += 4) {
            c0 = fmaf(br[e+0], watt[e+0], c0);
            c1 = fmaf(br[e+1], watt[e+1], c1);
            c2 = fmaf(br[e+2], watt[e+2], c2);
            c3 = fmaf(br[e+3], watt[e+3], c3);
        }
        g_C[hh] = (c0+c1)+(c2+c3);
    }
}

// ---------------- generic 128x128x8 fp32 GEMM, double-buffered -------------
// EPI==0 : C=g_Z  = tanh(A@B + bias);      A=x (param), B=W_ez, K=1024, ldb=1024
// EPI==1 : C=g_H1 = gelu(A@B + bias), per-head (blockIdx.z), logits epilogue;
//          A=g_HLN (+h*128), B=ff_W1 (+h*128*128), K=128, ldb=128
// EPI==2 : C=g_P  = A@B + sum_h scores*b2;  A=g_G, B=ff_W2_flat, K=1024, ldb=1024
template<int EPI>
__global__ void __launch_bounds__(256, 2) gemm128(
    const float* __restrict__ Aext, const float* __restrict__ Bm,
    const float* __restrict__ bias, const float* __restrict__ aux,
    int K, int ldb)
{
    const float* A = (EPI==0) ? Aext : (EPI==1) ? g_HLN : g_G;
    float*       C = (EPI==0) ? g_Z  : (EPI==1) ? g_H1  : g_P;

    __shared__ float As[2][8][128];
    __shared__ float Bs[2][8][128];

    const int tid = threadIdx.x;
    const int bx  = blockIdx.x;
    const int by  = blockIdx.y;
    const int h   = (EPI==1) ? (int)blockIdx.z : 0;

    const int tx = tid & 15;          // 0..15 -> N
    const int ty = tid >> 4;          // 0..15 -> M
    const int arow = tid >> 1;        // 0..127
    const int ac4  = (tid & 1) * 4;   // 0 or 4
    const int brow = tid >> 5;        // 0..7
    const int bc4  = (tid & 31) * 4;  // 0..124

    const float* Ag = A + ((EPI==1) ? (size_t)h*DD : (size_t)0)
                        + (size_t)(by*128 + arow)*1024 + ac4;
    const float* Bg = Bm + ((EPI==1) ? (size_t)h*DD*DD : (size_t)0)
                         + (size_t)brow*ldb + (size_t)bx*128 + bc4;

    float4 ar = *(const float4*)Ag;
    float4 br = *(const float4*)Bg;

    As[0][ac4+0][arow] = ar.x;
    As[0][ac4+1][arow] = ar.y;
    As[0][ac4+2][arow] = ar.z;
    As[0][ac4+3][arow] = ar.w;
    *(float4*)&Bs[0][brow][bc4] = br;
    __syncthreads();

    float acc[8][8];
    #pragma unroll
    for (int i = 0; i < 8; i++)
        #pragma unroll
        for (int j = 0; j < 8; j++) acc[i][j] = 0.f;

    const int nk = K >> 3;
    for (int kt = 0; kt < nk; kt++) {
        const int cur = kt & 1;
        const int nxt = cur ^ 1;
        if (kt + 1 < nk) {
            ar = *(const float4*)(Ag + (size_t)(kt+1)*8);
            br = *(const float4*)(Bg + (size_t)(kt+1)*8*ldb);
        }
        #pragma unroll
        for (int k = 0; k < 8; k++) {
            float a[8], b[8];
            *(float4*)(a)   = *(float4*)&As[cur][k][ty*8];
            *(float4*)(a+4) = *(float4*)&As[cur][k][ty*8+4];
            *(float4*)(b)   = *(float4*)&Bs[cur][k][tx*8];
            *(float4*)(b+4) = *(float4*)&Bs[cur][k][tx*8+4];
            #pragma unroll
            for (int i = 0; i < 8; i++)
                #pragma unroll
                for (int j = 0; j < 8; j++)
                    acc[i][j] = fmaf(a[i], b[j], acc[i][j]);
        }
        if (kt + 1 < nk) {
            As[nxt][ac4+0][arow] = ar.x;
            As[nxt][ac4+1][arow] = ar.y;
            As[nxt][ac4+2][arow] = ar.z;
            As[nxt][ac4+3][arow] = ar.w;
            *(float4*)&Bs[nxt][brow][bc4] = br;
        }
        __syncthreads();
    }

    // ------------- epilogue -------------
    const int colBase = (EPI==1) ? h*DD : bx*128;
    const int rBase   = by*128 + ty*8;
    #pragma unroll
    for (int i = 0; i < 8; i++) {
        const int r = rBase + i;
        float logit = 0.f;
        float s8[8];
        if (EPI==2) {
            #pragma unroll
            for (int h2 = 0; h2 < 8; h2++) s8[h2] = g_SC[(size_t)r*8 + h2];
        }
        #pragma unroll
        for (int j = 0; j < 8; j++) {
            const int c = colBase + tx*8 + j;
            float v = acc[i][j];
            if (EPI==0) {
                v += bias[c];
                v = tanhf(v);
            } else if (EPI==1) {
                v += bias[c];                       // bias = ff_b1, c = h*128+e
                v = 0.5f * v * (1.f + erff(v * 0.70710678118654752f));
                logit = fmaf(v, g_V[c], logit);     // g_V layout [h][e] == c
            } else {
                float bb = 0.f;
                #pragma unroll
                for (int h2 = 0; h2 < 8; h2++)
                    bb = fmaf(s8[h2], aux[(size_t)h2*EE + c], bb);  // aux = ff_b2
                v += bb;
            }
            C[(size_t)r*1024 + c] = v;
        }
        if (EPI==1) {
            // reduce logit over the 16 lanes sharing this row (same ty)
            #pragma unroll
            for (int off = 8; off >= 1; off >>= 1)
                logit += __shfl_xor_sync(0xffffffffu, logit, off);
            if (tx == 0) g_LG[(size_t)r*8 + h] = logit + g_C[h];
        }
    }
}

// ---------------- K2: sequential gated scan + per-step LN -------------------
// One warp per (b,h) sequence; 4 d's per lane (d = lane + 32*i).
__global__ void scan_kernel(const float* __restrict__ Uh,
                            const float* __restrict__ Uz,
                            const float* __restrict__ Bu,
                            const float* __restrict__ Lg,
                            const float* __restrict__ Lb)
{
    const int bidx = blockIdx.x;        // 32 = B*H
    const int b  = bidx >> 3;
    const int hh = bidx & 7;
    const int lane = threadIdx.x;       // 32

    float uh[4], uz[4], bu[4], lg[4], lb[4], h[4];
    #pragma unroll
    for (int i = 0; i < 4; i++) {
        const int d = lane + 32*i;
        uh[i] = Uh[(size_t)hh*DD*DD + (size_t)d*(DD+1)];
        uz[i] = Uz[(size_t)hh*DD*DD + (size_t)d*(DD+1)];
        bu[i] = Bu[hh*DD + d];
        lg[i] = Lg[d];
        lb[i] = Lb[d];
        h[i]  = 0.f;
    }

    const float* zp = g_Z  + (size_t)b*SS*EE + hh*DD + lane;
    float*       sp = g_ST + (size_t)b*SS*EE + hh*DD + lane;

    float z0[4], z1[4];
    #pragma unroll
    for (int i = 0; i < 4; i++) z0[i] = zp[32*i];
    #pragma unroll
    for (int i = 0; i < 4; i++) z1[i] = zp[1024 + 32*i];

    for (int s = 0; s < SS; s++) {
        float z2[4] = {0.f, 0.f, 0.f, 0.f};
        if (s + 2 < SS) {
            const float* p = zp + (size_t)(s+2)*EE;
            #pragma unroll
            for (int i = 0; i < 4; i++) z2[i] = p[32*i];
        }
        float hn[4];
        float s1 = 0.f, s2 = 0.f;
        #pragma unroll
        for (int i = 0; i < 4; i++) {
            float t = fmaf(h[i], uh[i], fmaf(z0[i], uz[i], bu[i]));
            float u = __fdividef(1.f, 1.f + __expf(-t));
            float v = fmaf(u, h[i] - z0[i], z0[i]);   // u*h + (1-u)*z
            hn[i] = v;
            s1 += v;
            s2 = fmaf(v, v, s2);
        }
        #pragma unroll
        for (int off = 16; off >= 1; off >>= 1) {
            s1 += __shfl_xor_sync(0xffffffffu, s1, off);
            s2 += __shfl_xor_sync(0xffffffffu, s2, off);
        }
        const float mean = s1 * (1.f/128.f);
        const float var  = fmaf(s2, 1.f/128.f, -mean*mean);
        const float rstd = rsqrtf(var + EPSF);
        float* so = sp + (size_t)s*EE;
        #pragma unroll
        for (int i = 0; i < 4; i++) {
            float o = fmaf((hn[i] - mean) * rstd, lg[i], lb[i]);
            h[i] = o;
            so[32*i] = o;
        }
        #pragma unroll
        for (int i = 0; i < 4; i++) { z0[i] = z1[i]; z1[i] = z2[i]; }
    }
}

// ---------------- K3: hln = LN(states * os_diag) per (t,h) row --------------
__global__ void head_ln(const float* __restrict__ OS,
                        const float* __restrict__ fg,
                        const float* __restrict__ fb)
{
    const int r    = blockIdx.x*8 + (threadIdx.x >> 5);   // row = t*8 + h
    const int lane = threadIdx.x & 31;
    const int hh   = r & 7;

    const float4 v = ((const float4*)(g_ST + (size_t)r*128))[lane];
    const int d0 = lane*4;
    const float* osb = OS + (size_t)hh*DD*DD;
    const float o0 = osb[(size_t)(d0+0)*(DD+1)];
    const float o1 = osb[(size_t)(d0+1)*(DD+1)];
    const float o2 = osb[(size_t)(d0+2)*(DD+1)];
    const float o3 = osb[(size_t)(d0+3)*(DD+1)];
    const float y0 = v.x*o0, y1 = v.y*o1, y2 = v.z*o2, y3 = v.w*o3;

    float s1 = (y0+y1)+(y2+y3);
    float s2 = fmaf(y0,y0, fmaf(y1,y1, fmaf(y2,y2, y3*y3)));
    #pragma unroll
    for (int off = 16; off >= 1; off >>= 1) {
        s1 += __shfl_xor_sync(0xffffffffu, s1, off);
        s2 += __shfl_xor_sync(0xffffffffu, s2, off);
    }
    const float mean = s1 * (1.f/128.f);
    const float var  = fmaf(s2, 1.f/128.f, -mean*mean);
    const float rstd = rsqrtf(var + EPSF);

    const float4 gv = ((const float4*)(fg + hh*128))[lane];
    const float4 bv = ((const float4*)(fb + hh*128))[lane];
    float4 o;
    o.x = fmaf((y0-mean)*rstd, gv.x, bv.x);
    o.y = fmaf((y1-mean)*rstd, gv.y, bv.y);
    o.z = fmaf((y2-mean)*rstd, gv.z, bv.z);
    o.w = fmaf((y3-mean)*rstd, gv.w, bv.w);
    ((float4*)(g_HLN + (size_t)r*128))[lane] = o;
}

// ---------------- K5: softmax over heads + scale h1 -> g --------------------
__global__ void softmax_scale()
{
    const int t    = blockIdx.x*8 + (threadIdx.x >> 5);
    const int lane = threadIdx.x & 31;

    float l[8];
    #pragma unroll
    for (int h2 = 0; h2 < 8; h2++) l[h2] = g_LG[(size_t)t*8 + h2];
    float m = l[0];
    #pragma unroll
    for (int h2 = 1; h2 < 8; h2++) m = fmaxf(m, l[h2]);
    float ssum = 0.f;
    #pragma unroll
    for (int h2 = 0; h2 < 8; h2++) { l[h2] = __expf(l[h2]-m); ssum += l[h2]; }
    const float inv = __fdividef(1.f, ssum);

    const float4* in  = (const float4*)(g_H1 + (size_t)t*1024);
    float4*       out = (float4*)      (g_G  + (size_t)t*1024);
    #pragma unroll
    for (int i = 0; i < 8; i++) {                 // chunk i == head i
        const float sh = l[i]*inv;
        float4 v = in[i*32 + lane];
        v.x *= sh; v.y *= sh; v.z *= sh; v.w *= sh;
        out[i*32 + lane] = v;
    }
    if (lane < 8) g_SC[(size_t)t*8 + lane] = l[lane]*inv;
}

// ---------------- K7: final LN over E ---------------------------------------
__global__ void final_ln(const float* __restrict__ lg_,
                         const float* __restrict__ lb_,
                         float* __restrict__ out)
{
    __shared__ float sm[16];
    const int t   = blockIdx.x;
    const int tid = threadIdx.x;       // 256

    const float4 v = ((const float4*)(g_P + (size_t)t*1024))[tid];
    float s1 = (v.x+v.y)+(v.z+v.w);
    float s2 = fmaf(v.x,v.x, fmaf(v.y,v.y, fmaf(v.z,v.z, v.w*v.w)));
    #pragma unroll
    for (int off = 16; off >= 1; off >>= 1) {
        s1 += __shfl_xor_sync(0xffffffffu, s1, off);
        s2 += __shfl_xor_sync(0xffffffffu, s2, off);
    }
    const int w = tid >> 5, lane = tid & 31;
    if (lane == 0) { sm[w] = s1; sm[8+w] = s2; }
    __syncthreads();
    float t1 = 0.f, t2 = 0.f;
    #pragma unroll
    for (int w2 = 0; w2 < 8; w2++) { t1 += sm[w2]; t2 += sm[8+w2]; }
    const float mean = t1 * (1.f/1024.f);
    const float var  = fmaf(t2, 1.f/1024.f, -mean*mean);
    const float rstd = rsqrtf(var + EPSF);

    const float4 g4 = ((const float4*)lg_)[tid];
    const float4 b4 = ((const float4*)lb_)[tid];
    float4 o;
    o.x = fmaf((v.x-mean)*rstd, g4.x, b4.x);
    o.y = fmaf((v.y-mean)*rstd, g4.y, b4.y);
    o.z = fmaf((v.z-mean)*rstd, g4.z, b4.z);
    o.w = fmaf((v.w-mean)*rstd, g4.w, b4.w);
    ((float4*)(out + (size_t)t*1024))[tid] = o;
}

// ---------------- launch ----------------------------------------------------
extern "C" void kernel_launch(void* const* d_in, const int* in_sizes, int n_in,
                              void* d_out, int out_size)
{
    const float* x      = (const float*)d_in[0];
    const float* W_ez   = (const float*)d_in[1];
    const float* b_ez   = (const float*)d_in[2];
    const float* U_h    = (const float*)d_in[3];
    const float* U_z    = (const float*)d_in[4];
    const float* b_u    = (const float*)d_in[5];
    const float* out_sh = (const float*)d_in[6];
    const float* lns_g  = (const float*)d_in[7];
    const float* lns_b  = (const float*)d_in[8];
    const float* ffln_g = (const float*)d_in[9];
    const float* ffln_b = (const float*)d_in[10];
    const float* ff_W1  = (const float*)d_in[11];
    const float* ff_b1  = (const float*)d_in[12];
    const float* ff_W2  = (const float*)d_in[13];
    const float* ff_b2  = (const float*)d_in[14];
    const float* w_att  = (const float*)d_in[15];
    // d_in[16] = b_att: adds equally to all head logits -> cancels in softmax
    const float* lno_g  = (const float*)d_in[17];
    const float* lno_b  = (const float*)d_in[18];
    float* out = (float*)d_out;

    prep_v<<<HH, DD>>>(ff_W2, ff_b2, w_att);

    // z = tanh(x @ W_ez + b_ez)
    gemm128<0><<<dim3(EE/128, TT/128), 256>>>(x, W_ez, b_ez, nullptr, EE, EE);

    // sequential gated scan with per-step LN
    scan_kernel<<<BB*HH, 32>>>(U_h, U_z, b_u, lns_g, lns_b);

    // hln = LN(states * os_diag)
    head_ln<<<TT*HH/8, 256>>>(out_sh, ffln_g, ffln_b);

    // h1 = gelu(hln @ W1[h] + b1[h]) per head; logits in epilogue
    gemm128<1><<<dim3(1, TT/128, HH), 256>>>(nullptr, ff_W1, ff_b1, nullptr, DD, DD);

    // softmax over heads; g = score * h1
    softmax_scale<<<TT/8, 256>>>();

    // weighted = g @ W2_flat + sum_h s_h * b2[h]
    gemm128<2><<<dim3(EE/128, TT/128), 256>>>(nullptr, ff_W2, nullptr, ff_b2, EE, EE);

    // final LN -> output
    final_ln<<<TT, 256>>>(lno_g, lno_b, out);
}

// round 3
// speedup vs baseline: 1.0541x; 1.0541x over previous
#include <cuda_runtime.h>
#include <math.h>
#include <stdint.h>

// Problem constants
#define BB 4
#define SS 2048
#define EE 1024
#define HH 8
#define DD 128
#define TT (BB*SS)          // 8192 tokens
#define EPSF 1e-5f

// ---------------- scratch (device globals; no allocations allowed) ----------
__device__ float g_Z  [TT*EE];   // tanh(x@W_ez)          [t][h*128+d]
__device__ float g_ST [TT*EE];   // scan states           [t][h*128+d]
__device__ float g_HLN[TT*EE];   // LN(states*os_diag)    [t][h*128+d]
__device__ float g_H1 [TT*EE];   // gelu FFN hidden       [t][h*128+e]
__device__ float g_G  [TT*EE];   // score-scaled h1       [t][h*128+e]
__device__ float g_P  [TT*EE];   // pre-LN output         [t][e]
__device__ float g_LG [TT*HH];   // logits
__device__ float g_SC [TT*HH];   // softmax scores
__device__ float g_V  [HH*DD];   // W2[h] @ w_att
__device__ float g_C  [HH];      // b2[h] . w_att
__device__ float g_WezT[EE*EE];  // W_ez transposed  [n][k]
__device__ float g_W2T [EE*EE];  // ff_W2 transposed [n][k]

// ---------------- tf32 helpers ----------------------------------------------
__device__ __forceinline__ uint32_t f2tf(float x) {
    uint32_t u;
    asm("cvt.rna.tf32.f32 %0, %1;" : "=r"(u) : "f"(x));
    return u;
}

__device__ __forceinline__ void mma8(float* c, const uint32_t* a, const uint32_t* b) {
    asm volatile("mma.sync.aligned.m16n8k8.row.col.f32.tf32.tf32.f32 "
        "{%0,%1,%2,%3}, {%4,%5,%6,%7}, {%8,%9}, {%0,%1,%2,%3};"
        : "+f"(c[0]), "+f"(c[1]), "+f"(c[2]), "+f"(c[3])
        : "r"(a[0]), "r"(a[1]), "r"(a[2]), "r"(a[3]), "r"(b[0]), "r"(b[1]));
}

// ---------------- transpose 1024x1024: out[n][k] = in[k][n] ------------------
__global__ void transpose1024(const float* __restrict__ in, float* __restrict__ out)
{
    __shared__ float tile[32][33];
    const int x = blockIdx.x*32 + threadIdx.x;
    const int y = blockIdx.y*32 + threadIdx.y;
    #pragma unroll
    for (int j = 0; j < 32; j += 8)
        tile[threadIdx.y + j][threadIdx.x] = in[(size_t)(y + j)*EE + x];
    __syncthreads();
    const int x2 = blockIdx.y*32 + threadIdx.x;
    const int y2 = blockIdx.x*32 + threadIdx.y;
    #pragma unroll
    for (int j = 0; j < 32; j += 8)
        out[(size_t)(y2 + j)*EE + x2] = tile[threadIdx.x][threadIdx.y + j];
}

// ---------------- K0: precompute v[h,d] = sum_e W2[h,d,e]*w_att[e] ----------
__global__ void prep_v(const float* __restrict__ W2,
                       const float* __restrict__ b2,
                       const float* __restrict__ watt)
{
    int hh = blockIdx.x;
    int d  = threadIdx.x;
    const float* row = W2 + ((size_t)hh*DD + d)*EE;
    float a0=0.f,a1=0.f,a2=0.f,a3=0.f;
    for (int e = 0; e < EE; e += 4) {
        a0 = fmaf(row[e+0], watt[e+0], a0);
        a1 = fmaf(row[e+1], watt[e+1], a1);
        a2 = fmaf(row[e+2], watt[e+2], a2);
        a3 = fmaf(row[e+3], watt[e+3], a3);
    }
    g_V[hh*DD + d] = (a0+a1)+(a2+a3);
    if (d == 0) {
        const float* br = b2 + (size_t)hh*EE;
        float c0=0.f;
        for (int e = 0; e < EE; e++) c0 = fmaf(br[e], watt[e], c0);
        g_C[hh] = c0;
    }
}

// ============ mma.sync tf32 3-pass GEMM: C[8192,1024] = epi(A @ Bt^T) ========
// A [8192,1024] row-major. Bt [1024][1024] = W^T (n-major rows of k).
// CTA 128x128, 8 warps (2m x 4n), warp tile 64x32, K-chunk 16.
// EPI==0: C=g_Z = tanh(v + bias[c]),  A=x
// EPI==2: C=g_P = v + sum_h g_SC[r][h]*bias[h*1024+c],  A=g_G
#define LDP 20   // padded row stride (floats) in smem: conflict-free frag loads
template<int EPI>
__global__ void __launch_bounds__(256) mma_gemm(
    const float* __restrict__ Aext, const float* __restrict__ Bt,
    const float* __restrict__ bias)
{
    __shared__ float As[2][128*LDP];
    __shared__ float Bs[2][128*LDP];

    const float* A = (EPI==0) ? Aext : g_G;
    float*       C = (EPI==0) ? g_Z  : g_P;

    const int tid  = threadIdx.x;
    const int wid  = tid >> 5;
    const int lane = tid & 31;
    const int wm   = wid >> 2;        // 0..1
    const int wn   = wid & 3;         // 0..3

    const int m0 = blockIdx.y * 128;
    const int n0 = blockIdx.x * 128;

    // loader mapping: each thread loads 8 floats (2 float4) of one row
    const int lrow = tid >> 1;        // 0..127
    const int lhalf = (tid & 1) * 8;  // 0 or 8
    const float* Ag = A  + (size_t)(m0 + lrow)*EE + lhalf;
    const float* Bg = Bt + (size_t)(n0 + lrow)*EE + lhalf;
    const int sdst = lrow*LDP + lhalf;

    // prologue: chunk 0
    float4 pa0 = *(const float4*)(Ag);
    float4 pa1 = *(const float4*)(Ag + 4);
    float4 pb0 = *(const float4*)(Bg);
    float4 pb1 = *(const float4*)(Bg + 4);
    *(float4*)&As[0][sdst]     = pa0;
    *(float4*)&As[0][sdst + 4] = pa1;
    *(float4*)&Bs[0][sdst]     = pb0;
    *(float4*)&Bs[0][sdst + 4] = pb1;
    __syncthreads();

    float acc[4][4][4];
    #pragma unroll
    for (int i = 0; i < 4; i++)
        #pragma unroll
        for (int j = 0; j < 4; j++)
            #pragma unroll
            for (int q = 0; q < 4; q++) acc[i][j][q] = 0.f;

    const int r = lane >> 2;          // 0..7
    const int cq = lane & 3;          // 0..3

    const int NKT = EE / 16;          // 64 chunks
    #pragma unroll 1
    for (int kt = 0; kt < NKT; kt++) {
        const int cur = kt & 1;
        if (kt + 1 < NKT) {
            const int ko = (kt + 1) * 16;
            pa0 = *(const float4*)(Ag + ko);
            pa1 = *(const float4*)(Ag + ko + 4);
            pb0 = *(const float4*)(Bg + ko);
            pb1 = *(const float4*)(Bg + ko + 4);
        }

        #pragma unroll
        for (int s = 0; s < 2; s++) {
            const float* as = &As[cur][s*8 + cq];
            const float* bs = &Bs[cur][s*8 + cq];
            uint32_t ah[16], al[16], bh[8], bl[8];
            #pragma unroll
            for (int mi = 0; mi < 4; mi++) {
                const int mb = (wm*64 + mi*16 + r)*LDP;
                float a0 = as[mb];
                float a1 = as[mb + 8*LDP];
                float a2 = as[mb + 4];
                float a3 = as[mb + 8*LDP + 4];
                uint32_t h0 = f2tf(a0), h1 = f2tf(a1), h2 = f2tf(a2), h3 = f2tf(a3);
                ah[mi*4+0] = h0; ah[mi*4+1] = h1; ah[mi*4+2] = h2; ah[mi*4+3] = h3;
                al[mi*4+0] = f2tf(a0 - __uint_as_float(h0));
                al[mi*4+1] = f2tf(a1 - __uint_as_float(h1));
                al[mi*4+2] = f2tf(a2 - __uint_as_float(h2));
                al[mi*4+3] = f2tf(a3 - __uint_as_float(h3));
            }
            #pragma unroll
            for (int ni = 0; ni < 4; ni++) {
                const int nb = (wn*32 + ni*8 + r)*LDP;
                float b0 = bs[nb];
                float b1 = bs[nb + 4];
                uint32_t h0 = f2tf(b0), h1 = f2tf(b1);
                bh[ni*2+0] = h0; bh[ni*2+1] = h1;
                bl[ni*2+0] = f2tf(b0 - __uint_as_float(h0));
                bl[ni*2+1] = f2tf(b1 - __uint_as_float(h1));
            }
            // pass 1: hi*hi
            #pragma unroll
            for (int mi = 0; mi < 4; mi++)
                #pragma unroll
                for (int ni = 0; ni < 4; ni++)
                    mma8(acc[mi][ni], &ah[mi*4], &bh[ni*2]);
            // pass 2: lo*hi
            #pragma unroll
            for (int mi = 0; mi < 4; mi++)
                #pragma unroll
                for (int ni = 0; ni < 4; ni++)
                    mma8(acc[mi][ni], &al[mi*4], &bh[ni*2]);
            // pass 3: hi*lo
            #pragma unroll
            for (int mi = 0; mi < 4; mi++)
                #pragma unroll
                for (int ni = 0; ni < 4; ni++)
                    mma8(acc[mi][ni], &ah[mi*4], &bl[ni*2]);
        }

        if (kt + 1 < NKT) {
            const int nxt = cur ^ 1;
            *(float4*)&As[nxt][sdst]     = pa0;
            *(float4*)&As[nxt][sdst + 4] = pa1;
            *(float4*)&Bs[nxt][sdst]     = pb0;
            *(float4*)&Bs[nxt][sdst + 4] = pb1;
        }
        __syncthreads();
    }

    // ---------------- epilogue ----------------
    #pragma unroll
    for (int mi = 0; mi < 4; mi++) {
        const int row0 = m0 + wm*64 + mi*16 + r;    // and row0+8
        float sA[8], sB[8];
        if (EPI == 2) {
            #pragma unroll
            for (int h2 = 0; h2 < 8; h2++) {
                sA[h2] = g_SC[(size_t)row0*8 + h2];
                sB[h2] = g_SC[(size_t)(row0+8)*8 + h2];
            }
        }
        #pragma unroll
        for (int ni = 0; ni < 4; ni++) {
            const int col = n0 + wn*32 + ni*8 + 2*cq;
            float v0 = acc[mi][ni][0], v1 = acc[mi][ni][1];
            float v2 = acc[mi][ni][2], v3 = acc[mi][ni][3];
            if (EPI == 0) {
                v0 = tanhf(v0 + bias[col]);
                v1 = tanhf(v1 + bias[col+1]);
                v2 = tanhf(v2 + bias[col]);
                v3 = tanhf(v3 + bias[col+1]);
            } else {
                float b00=0.f, b01=0.f, b10=0.f, b11=0.f;
                #pragma unroll
                for (int h2 = 0; h2 < 8; h2++) {
                    const float w0 = bias[(size_t)h2*EE + col];
                    const float w1 = bias[(size_t)h2*EE + col + 1];
                    b00 = fmaf(sA[h2], w0, b00);
                    b01 = fmaf(sA[h2], w1, b01);
                    b10 = fmaf(sB[h2], w0, b10);
                    b11 = fmaf(sB[h2], w1, b11);
                }
                v0 += b00; v1 += b01; v2 += b10; v3 += b11;
            }
            float2 p0; p0.x = v0; p0.y = v1;
            float2 p1; p1.x = v2; p1.y = v3;
            *(float2*)(C + (size_t)row0*EE + col)     = p0;
            *(float2*)(C + (size_t)(row0+8)*EE + col) = p1;
        }
    }
}

// ---------------- SIMT 128x128 GEMM for per-head FFN ------------------------
__global__ void __launch_bounds__(256, 2) gemm_ffn(
    const float* __restrict__ Bm, const float* __restrict__ bias)
{
    const float* A = g_HLN;
    float*       C = g_H1;

    __shared__ float As[2][8][128];
    __shared__ float Bs[2][8][128];

    const int tid = threadIdx.x;
    const int by  = blockIdx.y;
    const int h   = blockIdx.z;

    const int tx = tid & 15;
    const int ty = tid >> 4;
    const int arow = tid >> 1;
    const int ac4  = (tid & 1) * 4;
    const int brow = tid >> 5;
    const int bc4  = (tid & 31) * 4;

    const float* Ag = A + (size_t)h*DD + (size_t)(by*128 + arow)*1024 + ac4;
    const float* Bg = Bm + (size_t)h*DD*DD + (size_t)brow*DD + bc4;

    float4 ar = *(const float4*)Ag;
    float4 br = *(const float4*)Bg;

    As[0][ac4+0][arow] = ar.x;
    As[0][ac4+1][arow] = ar.y;
    As[0][ac4+2][arow] = ar.z;
    As[0][ac4+3][arow] = ar.w;
    *(float4*)&Bs[0][brow][bc4] = br;
    __syncthreads();

    float acc[8][8];
    #pragma unroll
    for (int i = 0; i < 8; i++)
        #pragma unroll
        for (int j = 0; j < 8; j++) acc[i][j] = 0.f;

    const int nk = DD >> 3;   // 16
    for (int kt = 0; kt < nk; kt++) {
        const int cur = kt & 1;
        const int nxt = cur ^ 1;
        if (kt + 1 < nk) {
            ar = *(const float4*)(Ag + (size_t)(kt+1)*8);
            br = *(const float4*)(Bg + (size_t)(kt+1)*8*DD);
        }
        #pragma unroll
        for (int k = 0; k < 8; k++) {
            float a[8], b[8];
            *(float4*)(a)   = *(float4*)&As[cur][k][ty*8];
            *(float4*)(a+4) = *(float4*)&As[cur][k][ty*8+4];
            *(float4*)(b)   = *(float4*)&Bs[cur][k][tx*8];
            *(float4*)(b+4) = *(float4*)&Bs[cur][k][tx*8+4];
            #pragma unroll
            for (int i = 0; i < 8; i++)
                #pragma unroll
                for (int j = 0; j < 8; j++)
                    acc[i][j] = fmaf(a[i], b[j], acc[i][j]);
        }
        if (kt + 1 < nk) {
            As[nxt][ac4+0][arow] = ar.x;
            As[nxt][ac4+1][arow] = ar.y;
            As[nxt][ac4+2][arow] = ar.z;
            As[nxt][ac4+3][arow] = ar.w;
            *(float4*)&Bs[nxt][brow][bc4] = br;
        }
        __syncthreads();
    }

    const int colBase = h*DD;
    const int rBase   = by*128 + ty*8;
    #pragma unroll
    for (int i = 0; i < 8; i++) {
        const int r = rBase + i;
        float logit = 0.f;
        #pragma unroll
        for (int j = 0; j < 8; j++) {
            const int c = colBase + tx*8 + j;
            float v = acc[i][j] + bias[c];
            v = 0.5f * v * (1.f + erff(v * 0.70710678118654752f));
            logit = fmaf(v, g_V[c], logit);
            C[(size_t)r*1024 + c] = v;
        }
        #pragma unroll
        for (int off = 8; off >= 1; off >>= 1)
            logit += __shfl_xor_sync(0xffffffffu, logit, off);
        if (tx == 0) g_LG[(size_t)r*8 + h] = logit + g_C[h];
    }
}

// ---------------- K2: sequential gated scan + per-step LN -------------------
__global__ void scan_kernel(const float* __restrict__ Uh,
                            const float* __restrict__ Uz,
                            const float* __restrict__ Bu,
                            const float* __restrict__ Lg,
                            const float* __restrict__ Lb)
{
    const int bidx = blockIdx.x;
    const int b  = bidx >> 3;
    const int hh = bidx & 7;
    const int lane = threadIdx.x;

    float uh[4], uz[4], bu[4], lg[4], lb[4], h[4];
    #pragma unroll
    for (int i = 0; i < 4; i++) {
        const int d = lane + 32*i;
        uh[i] = Uh[(size_t)hh*DD*DD + (size_t)d*(DD+1)];
        uz[i] = Uz[(size_t)hh*DD*DD + (size_t)d*(DD+1)];
        bu[i] = Bu[hh*DD + d];
        lg[i] = Lg[d];
        lb[i] = Lb[d];
        h[i]  = 0.f;
    }

    const float* zp = g_Z  + (size_t)b*SS*EE + hh*DD + lane;
    float*       sp = g_ST + (size_t)b*SS*EE + hh*DD + lane;

    float z0[4], z1[4];
    #pragma unroll
    for (int i = 0; i < 4; i++) z0[i] = zp[32*i];
    #pragma unroll
    for (int i = 0; i < 4; i++) z1[i] = zp[1024 + 32*i];

    for (int s = 0; s < SS; s++) {
        float z2[4] = {0.f, 0.f, 0.f, 0.f};
        if (s + 2 < SS) {
            const float* p = zp + (size_t)(s+2)*EE;
            #pragma unroll
            for (int i = 0; i < 4; i++) z2[i] = p[32*i];
        }
        float hn[4];
        float s1 = 0.f, s2 = 0.f;
        #pragma unroll
        for (int i = 0; i < 4; i++) {
            float t = fmaf(h[i], uh[i], fmaf(z0[i], uz[i], bu[i]));
            float u = __fdividef(1.f, 1.f + __expf(-t));
            float v = fmaf(u, h[i] - z0[i], z0[i]);
            hn[i] = v;
            s1 += v;
            s2 = fmaf(v, v, s2);
        }
        #pragma unroll
        for (int off = 16; off >= 1; off >>= 1) {
            s1 += __shfl_xor_sync(0xffffffffu, s1, off);
            s2 += __shfl_xor_sync(0xffffffffu, s2, off);
        }
        const float mean = s1 * (1.f/128.f);
        const float var  = fmaf(s2, 1.f/128.f, -mean*mean);
        const float rstd = rsqrtf(var + EPSF);
        float* so = sp + (size_t)s*EE;
        #pragma unroll
        for (int i = 0; i < 4; i++) {
            float o = fmaf((hn[i] - mean) * rstd, lg[i], lb[i]);
            h[i] = o;
            so[32*i] = o;
        }
        #pragma unroll
        for (int i = 0; i < 4; i++) { z0[i] = z1[i]; z1[i] = z2[i]; }
    }
}

// ---------------- K3: hln = LN(states * os_diag) per (t,h) row --------------
__global__ void head_ln(const float* __restrict__ OS,
                        const float* __restrict__ fg,
                        const float* __restrict__ fb)
{
    const int r    = blockIdx.x*8 + (threadIdx.x >> 5);
    const int lane = threadIdx.x & 31;
    const int hh   = r & 7;

    const float4 v = ((const float4*)(g_ST + (size_t)r*128))[lane];
    const int d0 = lane*4;
    const float* osb = OS + (size_t)hh*DD*DD;
    const float o0 = osb[(size_t)(d0+0)*(DD+1)];
    const float o1 = osb[(size_t)(d0+1)*(DD+1)];
    const float o2 = osb[(size_t)(d0+2)*(DD+1)];
    const float o3 = osb[(size_t)(d0+3)*(DD+1)];
    const float y0 = v.x*o0, y1 = v.y*o1, y2 = v.z*o2, y3 = v.w*o3;

    float s1 = (y0+y1)+(y2+y3);
    float s2 = fmaf(y0,y0, fmaf(y1,y1, fmaf(y2,y2, y3*y3)));
    #pragma unroll
    for (int off = 16; off >= 1; off >>= 1) {
        s1 += __shfl_xor_sync(0xffffffffu, s1, off);
        s2 += __shfl_xor_sync(0xffffffffu, s2, off);
    }
    const float mean = s1 * (1.f/128.f);
    const float var  = fmaf(s2, 1.f/128.f, -mean*mean);
    const float rstd = rsqrtf(var + EPSF);

    const float4 gv = ((const float4*)(fg + hh*128))[lane];
    const float4 bv = ((const float4*)(fb + hh*128))[lane];
    float4 o;
    o.x = fmaf((y0-mean)*rstd, gv.x, bv.x);
    o.y = fmaf((y1-mean)*rstd, gv.y, bv.y);
    o.z = fmaf((y2-mean)*rstd, gv.z, bv.z);
    o.w = fmaf((y3-mean)*rstd, gv.w, bv.w);
    ((float4*)(g_HLN + (size_t)r*128))[lane] = o;
}

// ---------------- K5: softmax over heads + scale h1 -> g --------------------
__global__ void softmax_scale()
{
    const int t    = blockIdx.x*8 + (threadIdx.x >> 5);
    const int lane = threadIdx.x & 31;

    float l[8];
    #pragma unroll
    for (int h2 = 0; h2 < 8; h2++) l[h2] = g_LG[(size_t)t*8 + h2];
    float m = l[0];
    #pragma unroll
    for (int h2 = 1; h2 < 8; h2++) m = fmaxf(m, l[h2]);
    float ssum = 0.f;
    #pragma unroll
    for (int h2 = 0; h2 < 8; h2++) { l[h2] = __expf(l[h2]-m); ssum += l[h2]; }
    const float inv = __fdividef(1.f, ssum);

    const float4* in  = (const float4*)(g_H1 + (size_t)t*1024);
    float4*       out = (float4*)      (g_G  + (size_t)t*1024);
    #pragma unroll
    for (int i = 0; i < 8; i++) {
        const float sh = l[i]*inv;
        float4 v = in[i*32 + lane];
        v.x *= sh; v.y *= sh; v.z *= sh; v.w *= sh;
        out[i*32 + lane] = v;
    }
    if (lane < 8) g_SC[(size_t)t*8 + lane] = l[lane]*inv;
}

// ---------------- K7: final LN over E ---------------------------------------
__global__ void final_ln(const float* __restrict__ lg_,
                         const float* __restrict__ lb_,
                         float* __restrict__ out)
{
    __shared__ float sm[16];
    const int t   = blockIdx.x;
    const int tid = threadIdx.x;

    const float4 v = ((const float4*)(g_P + (size_t)t*1024))[tid];
    float s1 = (v.x+v.y)+(v.z+v.w);
    float s2 = fmaf(v.x,v.x, fmaf(v.y,v.y, fmaf(v.z,v.z, v.w*v.w)));
    #pragma unroll
    for (int off = 16; off >= 1; off >>= 1) {
        s1 += __shfl_xor_sync(0xffffffffu, s1, off);
        s2 += __shfl_xor_sync(0xffffffffu, s2, off);
    }
    const int w = tid >> 5, lane = tid & 31;
    if (lane == 0) { sm[w] = s1; sm[8+w] = s2; }
    __syncthreads();
    float t1 = 0.f, t2 = 0.f;
    #pragma unroll
    for (int w2 = 0; w2 < 8; w2++) { t1 += sm[w2]; t2 += sm[8+w2]; }
    const float mean = t1 * (1.f/1024.f);
    const float var  = fmaf(t2, 1.f/1024.f, -mean*mean);
    const float rstd = rsqrtf(var + EPSF);

    const float4 g4 = ((const float4*)lg_)[tid];
    const float4 b4 = ((const float4*)lb_)[tid];
    float4 o;
    o.x = fmaf((v.x-mean)*rstd, g4.x, b4.x);
    o.y = fmaf((v.y-mean)*rstd, g4.y, b4.y);
    o.z = fmaf((v.z-mean)*rstd, g4.z, b4.z);
    o.w = fmaf((v.w-mean)*rstd, g4.w, b4.w);
    ((float4*)(out + (size_t)t*1024))[tid] = o;
}

// ---------------- launch ----------------------------------------------------
extern "C" void kernel_launch(void* const* d_in, const int* in_sizes, int n_in,
                              void* d_out, int out_size)
{
    const float* x      = (const float*)d_in[0];
    const float* W_ez   = (const float*)d_in[1];
    const float* b_ez   = (const float*)d_in[2];
    const float* U_h    = (const float*)d_in[3];
    const float* U_z    = (const float*)d_in[4];
    const float* b_u    = (const float*)d_in[5];
    const float* out_sh = (const float*)d_in[6];
    const float* lns_g  = (const float*)d_in[7];
    const float* lns_b  = (const float*)d_in[8];
    const float* ffln_g = (const float*)d_in[9];
    const float* ffln_b = (const float*)d_in[10];
    const float* ff_W1  = (const float*)d_in[11];
    const float* ff_b1  = (const float*)d_in[12];
    const float* ff_W2  = (const float*)d_in[13];
    const float* ff_b2  = (const float*)d_in[14];
    const float* w_att  = (const float*)d_in[15];
    // d_in[16] = b_att: cancels in softmax
    const float* lno_g  = (const float*)d_in[17];
    const float* lno_b  = (const float*)d_in[18];
    float* out = (float*)d_out;

    float* wezT; cudaGetSymbolAddress((void**)&wezT, g_WezT);
    float* w2T;  cudaGetSymbolAddress((void**)&w2T,  g_W2T);

    // prep (independent)
    transpose1024<<<dim3(32,32), dim3(32,8)>>>(W_ez, wezT);
    transpose1024<<<dim3(32,32), dim3(32,8)>>>(ff_W2, w2T);
    prep_v<<<HH, DD>>>(ff_W2, ff_b2, w_att);

    // z = tanh(x @ W_ez + b_ez)   [mma.sync tf32 3-pass]
    mma_gemm<0><<<dim3(EE/128, TT/128), 256>>>(x, wezT, b_ez);

    // sequential gated scan with per-step LN
    scan_kernel<<<BB*HH, 32>>>(U_h, U_z, b_u, lns_g, lns_b);

    // hln = LN(states * os_diag)
    head_ln<<<TT*HH/8, 256>>>(out_sh, ffln_g, ffln_b);

    // h1 = gelu(hln @ W1[h] + b1[h]) per head; logits in epilogue  [SIMT]
    gemm_ffn<<<dim3(1, TT/128, HH), 256>>>(ff_W1, ff_b1);

    // softmax over heads; g = score * h1
    softmax_scale<<<TT/8, 256>>>();

    // weighted = g @ W2 + sum_h s_h*b2   [mma.sync tf32 3-pass]
    mma_gemm<2><<<dim3(EE/128, TT/128), 256>>>(nullptr, w2T, ff_b2);

    // final LN -> output
    final_ln<<<TT, 256>>>(lno_g, lno_b, out);
}